// round 8
// baseline (speedup 1.0000x reference)
#include <cuda_runtime.h>
#include <cuda_fp16.h>

#define NN 100000
#define EE 1600000
#define HH 128
#define GG 1000
#define CC 10
#define LL 3
#define BN_EPS 1e-5f

// ---------------- scratch (static device globals; no allocation) ----------------
__device__ __half d_gh[NN * HH];    // fp16 dinv-scaled GEMM output (gather array)
__device__ float  d_pre[NN * HH];   // fp32 pre-BN activations
__device__ float  d_dinv[NN];
__device__ int    d_deg[NN];
__device__ int    d_rowstart[NN];
__device__ int    d_cursor[NN];
__device__ int    d_colsrc[EE];
__device__ float  d_bnsum[HH];
__device__ float  d_bnsq[HH];
__device__ float  d_scale[HH];
__device__ float  d_shift[HH];
__device__ float  d_pooled[GG * HH];
__device__ int    d_cnt[GG];
__device__ int    d_bsum[128];      // scan block sums (98 used)

// ---------------- graph preprocessing ----------------
__global__ void k_zero_deg() {
    int i = blockIdx.x * 256 + threadIdx.x;
    if (i < NN) d_deg[i] = 0;
}

__global__ void k_count(const int* __restrict__ ei) {
    int e = blockIdx.x * 256 + threadIdx.x;
    if (e >= EE) return;
    atomicAdd(&d_deg[ei[EE + e]], 1);
}

__global__ void k_scan1() {  // 98 blocks x 1024: per-block sum
    __shared__ int sh[1024];
    int i = blockIdx.x * 1024 + threadIdx.x;
    sh[threadIdx.x] = (i < NN) ? d_deg[i] : 0;
    __syncthreads();
    for (int s = 512; s > 0; s >>= 1) {
        if (threadIdx.x < s) sh[threadIdx.x] += sh[threadIdx.x + s];
        __syncthreads();
    }
    if (threadIdx.x == 0) d_bsum[blockIdx.x] = sh[0];
}

__global__ void k_scan2(int nb) {  // serial exclusive scan of 98 block sums
    if (threadIdx.x == 0 && blockIdx.x == 0) {
        int acc = 0;
        for (int b = 0; b < nb; b++) { int v = d_bsum[b]; d_bsum[b] = acc; acc += v; }
    }
}

__global__ void k_scan3() {  // intra-block exclusive scan + block offset
    __shared__ int sh[1024];
    int tid = threadIdx.x;
    int i = blockIdx.x * 1024 + tid;
    int v = (i < NN) ? d_deg[i] : 0;
    sh[tid] = v;
    __syncthreads();
    for (int off = 1; off < 1024; off <<= 1) {
        int tv = (tid >= off) ? sh[tid - off] : 0;
        __syncthreads();
        sh[tid] += tv;
        __syncthreads();
    }
    if (i < NN) {
        int excl = sh[tid] - v + d_bsum[blockIdx.x];
        d_rowstart[i] = excl;
        d_cursor[i]   = excl;
    }
}

__global__ void k_fill(const int* __restrict__ ei) {
    int e = blockIdx.x * 256 + threadIdx.x;
    if (e >= EE) return;
    int dd = ei[EE + e];
    int pos = atomicAdd(&d_cursor[dd], 1);
    d_colsrc[pos] = ei[e];
}

__global__ void k_dinv() {
    int i = blockIdx.x * 256 + threadIdx.x;
    if (i < NN) d_dinv[i] = rsqrtf(1.0f + (float)d_deg[i]);
}

// ---------------- GEMM: d_gh = fp16( dinv * (bn_relu(A) @ W) ) ----------------
// 256 rows x 128 cols per block, 512 threads, 8x8 micro-tile.
// layer==0: A = x raw. layer>0: A = d_pre with affine(scale,shift)+relu folded in.
#define GEMM_ROWS 256
#define GEMM_SMEM_FLOATS (16384 + GEMM_ROWS * 132 + 256)
#define GEMM_SMEM_BYTES  (GEMM_SMEM_FLOATS * 4)

__global__ __launch_bounds__(512, 1) void k_gemm(const float* __restrict__ x0,
                                                 const float* __restrict__ W,
                                                 int layer) {
    extern __shared__ float sm[];
    float* Ws  = sm;                             // [128][128]
    float* As  = sm + 16384;                     // [256][132]
    float* ssc = sm + 16384 + GEMM_ROWS * 132;   // [128]
    float* ssh = ssc + 128;                      // [128]

    int t = threadIdx.x;
    const float* A = (layer == 0) ? x0 : d_pre;
    bool aff = (layer != 0);

    if (t < 128) {
        ssc[t] = aff ? d_scale[t] : 1.0f;
        ssh[t] = aff ? d_shift[t] : 0.0f;
    }
    // load full W (128x128) : 4096 float4 / 512 threads = 8 each
#pragma unroll
    for (int i = 0; i < 8; i++) {
        int f = t + i * 512;
        int k = f >> 5;
        int j4 = (f & 31) * 4;
        *(float4*)&Ws[k * 128 + j4] = *(const float4*)&W[k * 128 + j4];
    }
    __syncthreads();  // ssc/ssh visible before A transform

    int blockRow = blockIdx.x * GEMM_ROWS;
    // load A tile (256x128): 8192 float4 / 512 = 16 each
#pragma unroll
    for (int i = 0; i < 16; i++) {
        int f = t + i * 512;
        int r = f >> 5;
        int k4 = (f & 31) * 4;
        int grow = blockRow + r;
        float4 a4 = make_float4(0.f, 0.f, 0.f, 0.f);
        if (grow < NN) a4 = *(const float4*)&A[grow * HH + k4];
        if (aff) {
            a4.x = fmaxf(fmaf(a4.x, ssc[k4 + 0], ssh[k4 + 0]), 0.f);
            a4.y = fmaxf(fmaf(a4.y, ssc[k4 + 1], ssh[k4 + 1]), 0.f);
            a4.z = fmaxf(fmaf(a4.z, ssc[k4 + 2], ssh[k4 + 2]), 0.f);
            a4.w = fmaxf(fmaf(a4.w, ssc[k4 + 3], ssh[k4 + 3]), 0.f);
        }
        *(float4*)&As[r * 132 + k4] = a4;
    }
    __syncthreads();

    int tx = t & 15;    // 16 col groups * 8 = 128 cols
    int ty = t >> 4;    // 32 row groups; rows = ty + 32*i, i<8
    float acc[8][8];
#pragma unroll
    for (int i = 0; i < 8; i++)
#pragma unroll
        for (int j = 0; j < 8; j++) acc[i][j] = 0.f;

#pragma unroll 8
    for (int k = 0; k < 128; k++) {
        float b[8];
        float4 b0  = *(float4*)&Ws[k * 128 + tx * 8];
        float4 b1v = *(float4*)&Ws[k * 128 + tx * 8 + 4];
        b[0] = b0.x; b[1] = b0.y; b[2] = b0.z; b[3] = b0.w;
        b[4] = b1v.x; b[5] = b1v.y; b[6] = b1v.z; b[7] = b1v.w;
        float a[8];
#pragma unroll
        for (int i = 0; i < 8; i++) a[i] = As[(ty + i * 32) * 132 + k];
#pragma unroll
        for (int i = 0; i < 8; i++)
#pragma unroll
            for (int j = 0; j < 8; j++) acc[i][j] = fmaf(a[i], b[j], acc[i][j]);
    }

#pragma unroll
    for (int i = 0; i < 8; i++) {
        int grow = blockRow + ty + i * 32;
        if (grow < NN) {
            float dv = d_dinv[grow];
            __half2 h[4];
#pragma unroll
            for (int q = 0; q < 4; q++)
                h[q] = __floats2half2_rn(acc[i][2 * q] * dv, acc[i][2 * q + 1] * dv);
            *(uint4*)&d_gh[grow * HH + tx * 8] = *(uint4*)h;
        }
    }
}

// ---------------- aggregation + combine + BN stats (fp16 gathers) ----------------
// 256 threads = 4 groups of 64 lanes; lane j handles features (2j, 2j+1) as half2.
// Each group processes rows base + 4*r + grp. 4-way edge unroll for MLP.
#define AGG_ROWS 64
__global__ __launch_bounds__(256) void k_agg(const float* __restrict__ bias) {
    int t = threadIdx.x;
    int j = t & 63;
    int grp = t >> 6;
    int base = blockIdx.x * AGG_ROWS;
    const __half2* g2 = (const __half2*)d_gh;
    float2* pre2 = (float2*)d_pre;
    float bx = bias[2 * j], by = bias[2 * j + 1];
    float lsx = 0.f, lsy = 0.f, lqx = 0.f, lqy = 0.f;
#pragma unroll 1
    for (int r = grp; r < AGG_ROWS; r += 4) {
        int d = base + r;
        if (d >= NN) break;
        float2 sf = __half22float2(g2[d * 64 + j]);  // self-loop (already dinv-scaled)
        float a0x = sf.x, a0y = sf.y;
        float a1x = 0.f, a1y = 0.f, a2x = 0.f, a2y = 0.f, a3x = 0.f, a3y = 0.f;
        int s0 = d_rowstart[d];
        int cnt = d_deg[d];
        int e = 0;
        for (; e + 3 < cnt; e += 4) {
            int s1 = d_colsrc[s0 + e];
            int s2 = d_colsrc[s0 + e + 1];
            int s3 = d_colsrc[s0 + e + 2];
            int s4 = d_colsrc[s0 + e + 3];
            float2 v1 = __half22float2(g2[s1 * 64 + j]);
            float2 v2 = __half22float2(g2[s2 * 64 + j]);
            float2 v3 = __half22float2(g2[s3 * 64 + j]);
            float2 v4 = __half22float2(g2[s4 * 64 + j]);
            a0x += v1.x; a0y += v1.y;
            a1x += v2.x; a1y += v2.y;
            a2x += v3.x; a2y += v3.y;
            a3x += v4.x; a3y += v4.y;
        }
        for (; e < cnt; e++) {
            float2 v = __half22float2(g2[d_colsrc[s0 + e] * 64 + j]);
            a0x += v.x; a0y += v.y;
        }
        float dv = d_dinv[d];
        float vx = fmaf(dv, (a0x + a1x) + (a2x + a3x), bx);
        float vy = fmaf(dv, (a0y + a1y) + (a2y + a3y), by);
        pre2[d * 64 + j] = make_float2(vx, vy);
        lsx += vx; lqx = fmaf(vx, vx, lqx);
        lsy += vy; lqy = fmaf(vy, vy, lqy);
    }
    atomicAdd(&d_bnsum[2 * j], lsx);
    atomicAdd(&d_bnsum[2 * j + 1], lsy);
    atomicAdd(&d_bnsq[2 * j], lqx);
    atomicAdd(&d_bnsq[2 * j + 1], lqy);
}

__global__ void k_bnfin(const float* __restrict__ gamma, const float* __restrict__ beta) {
    int j = threadIdx.x;
    float mean = d_bnsum[j] * (1.0f / NN);
    float var  = d_bnsq[j] * (1.0f / NN) - mean * mean;
    float s = gamma[j] * rsqrtf(var + BN_EPS);
    d_scale[j] = s;
    d_shift[j] = beta[j] - mean * s;
    // zero-after-read: keeps steady-state invariant under graph replay
    d_bnsum[j] = 0.f;
    d_bnsq[j]  = 0.f;
}

// ---------------- global mean pool (batch is sorted) ----------------
#define POOL_R 256
__global__ void k_pool(const int* __restrict__ batch) {
    int j = threadIdx.x;  // 0..127
    int base = blockIdx.x * POOL_R;
    if (base >= NN) return;
    int end = base + POOL_R;
    if (end > NN) end = NN;
    int cur = batch[base];
    float acc = 0.f;
    int run = 0;
    float sc = d_scale[j], sh = d_shift[j];
    for (int row = base; row < end; row++) {
        int b = batch[row];
        if (b != cur) {
            atomicAdd(&d_pooled[cur * HH + j], acc);
            if (j == 0) atomicAdd(&d_cnt[cur], run);
            acc = 0.f; run = 0; cur = b;
        }
        float v = d_pre[row * HH + j];
        v = fmaxf(fmaf(v, sc, sh), 0.f);
        acc += v;
        run++;
    }
    atomicAdd(&d_pooled[cur * HH + j], acc);
    if (j == 0) atomicAdd(&d_cnt[cur], run);
}

// ---------------- classifier MLP (zeroes its pooled row after reading) ----------------
__global__ void k_mlp(const float* __restrict__ w1, const float* __restrict__ b1,
                      const float* __restrict__ w2, const float* __restrict__ b2,
                      float* __restrict__ out) {
    __shared__ float p[128];
    __shared__ float z[64];
    int t = threadIdx.x;  // 0..63
    int g = blockIdx.x;
    float c = fmaxf((float)d_cnt[g], 1.0f);
    float inv = 1.0f / c;
    p[t]      = d_pooled[g * HH + t] * inv;
    p[t + 64] = d_pooled[g * HH + 64 + t] * inv;
    __syncthreads();
    // zero-after-read for next replay
    d_pooled[g * HH + t] = 0.f;
    d_pooled[g * HH + 64 + t] = 0.f;
    if (t == 0) d_cnt[g] = 0;
    float a = b1[t];
#pragma unroll 8
    for (int k = 0; k < 128; k++) a = fmaf(p[k], w1[k * 64 + t], a);
    z[t] = fmaxf(a, 0.f);
    __syncthreads();
    if (t < CC) {
        float o = b2[t];
#pragma unroll
        for (int q = 0; q < 64; q++) o = fmaf(z[q], w2[q * CC + t], o);
        out[g * CC + t] = o;
    }
}

// ---------------- launch ----------------
extern "C" void kernel_launch(void* const* d_in, const int* in_sizes, int n_in,
                              void* d_out, int out_size) {
    const float* x      = (const float*)d_in[0];
    const float* conv_w = (const float*)d_in[1];
    const float* conv_b = (const float*)d_in[2];
    const float* bng    = (const float*)d_in[3];
    const float* bnb    = (const float*)d_in[4];
    const float* w1     = (const float*)d_in[5];
    const float* b1     = (const float*)d_in[6];
    const float* w2     = (const float*)d_in[7];
    const float* b2     = (const float*)d_in[8];
    const int*   ei     = (const int*)d_in[9];
    const int*   batch  = (const int*)d_in[10];
    float* out = (float*)d_out;

    cudaFuncSetAttribute(k_gemm, cudaFuncAttributeMaxDynamicSharedMemorySize,
                         GEMM_SMEM_BYTES);

    const int NB_SCAN = (NN + 1023) / 1024;  // 98

    // CSR build by dst + degrees
    k_zero_deg<<<(NN + 255) / 256, 256>>>();
    k_count<<<(EE + 255) / 256, 256>>>(ei);
    k_scan1<<<NB_SCAN, 1024>>>();
    k_scan2<<<1, 32>>>(NB_SCAN);
    k_scan3<<<NB_SCAN, 1024>>>();
    k_fill<<<(EE + 255) / 256, 256>>>(ei);
    k_dinv<<<(NN + 255) / 256, 256>>>();

    const int GEMM_GRID = (NN + GEMM_ROWS - 1) / GEMM_ROWS;  // 391
    for (int l = 0; l < LL; l++) {
        k_gemm<<<GEMM_GRID, 512, GEMM_SMEM_BYTES>>>(x, conv_w + l * HH * HH, l);
        k_agg<<<(NN + AGG_ROWS - 1) / AGG_ROWS, 256>>>(conv_b + l * HH);
        k_bnfin<<<1, 128>>>(bng + l * HH, bnb + l * HH);
    }

    k_pool<<<(NN + POOL_R - 1) / POOL_R, 128>>>(batch);
    k_mlp<<<GG, 64>>>(w1, b1, w2, b2, out);
}

// round 13
// speedup vs baseline: 1.2371x; 1.2371x over previous
#include <cuda_runtime.h>
#include <cuda_fp16.h>
#include <mma.h>
#include <cstdint>

using namespace nvcuda;

#define NN 100000
#define EE 1600000
#define HH 128
#define GG 1000
#define CC 10
#define LL 3
#define BN_EPS 1e-5f

// ---------------- scratch (static device globals; no allocation) ----------------
__device__ __half d_gh[NN * HH];      // fp16 dinv-scaled GEMM output (gather array)
__device__ __half d_preh[NN * HH];    // fp16 pre-BN activations
__device__ __half d_wh[LL * HH * HH]; // fp16 transposed weights: d_wh[l][n*128+k] = W[l][k][n]
__device__ float  d_dinv[NN];
__device__ int    d_deg[NN];
__device__ int    d_rowstart[NN];
__device__ int    d_cursor[NN];
__device__ int    d_colsrc[EE];
__device__ float  d_bnsum[HH];
__device__ float  d_bnsq[HH];
__device__ float  d_scale[HH];
__device__ float  d_shift[HH];
__device__ float  d_pooled[GG * HH];
__device__ int    d_cnt[GG];
__device__ int    d_bsum[128];        // scan block sums (98 used)

// ---------------- graph preprocessing ----------------
// launch idx 0: zero degrees + transpose/convert all 3 layer weights to fp16
__global__ void k_zero_deg(const float* __restrict__ conv_w) {
    int i = blockIdx.x * 256 + threadIdx.x;
    if (i < NN) d_deg[i] = 0;
    if (i < LL * HH * HH) {
        int l = i >> 14;
        int rem = i & 16383;
        int n = rem >> 7;
        int k = rem & 127;
        d_wh[(l << 14) + n * 128 + k] = __float2half(conv_w[(l << 14) + k * 128 + n]);
    }
}

__global__ void k_count(const int* __restrict__ ei) {
    int e = blockIdx.x * 256 + threadIdx.x;
    if (e >= EE) return;
    atomicAdd(&d_deg[ei[EE + e]], 1);
}

__global__ void k_scan1() {  // per-block degree sum; also computes dinv
    __shared__ int sh[1024];
    int i = blockIdx.x * 1024 + threadIdx.x;
    int v = (i < NN) ? d_deg[i] : 0;
    if (i < NN) d_dinv[i] = rsqrtf(1.0f + (float)v);
    sh[threadIdx.x] = v;
    __syncthreads();
    for (int s = 512; s > 0; s >>= 1) {
        if (threadIdx.x < s) sh[threadIdx.x] += sh[threadIdx.x + s];
        __syncthreads();
    }
    if (threadIdx.x == 0) d_bsum[blockIdx.x] = sh[0];
}

__global__ void k_scan2(int nb) {
    if (threadIdx.x == 0 && blockIdx.x == 0) {
        int acc = 0;
        for (int b = 0; b < nb; b++) { int v = d_bsum[b]; d_bsum[b] = acc; acc += v; }
    }
}

__global__ void k_scan3() {
    __shared__ int sh[1024];
    int tid = threadIdx.x;
    int i = blockIdx.x * 1024 + tid;
    int v = (i < NN) ? d_deg[i] : 0;
    sh[tid] = v;
    __syncthreads();
    for (int off = 1; off < 1024; off <<= 1) {
        int tv = (tid >= off) ? sh[tid - off] : 0;
        __syncthreads();
        sh[tid] += tv;
        __syncthreads();
    }
    if (i < NN) {
        int excl = sh[tid] - v + d_bsum[blockIdx.x];
        d_rowstart[i] = excl;
        d_cursor[i]   = excl;
    }
}

__global__ void k_fill(const int* __restrict__ ei) {
    int e = blockIdx.x * 256 + threadIdx.x;
    if (e >= EE) return;
    int dd = ei[EE + e];
    int pos = atomicAdd(&d_cursor[dd], 1);
    d_colsrc[pos] = ei[e];
}

// ---------------- wmma GEMM: d_gh = fp16( dinv * (bn_relu(A) @ W) ) ----------------
// 128 rows x 128 cols per CTA, 256 threads = 8 warps.
// Warp w: rows (w&3)*32..+31, cols (w>>2)*64..+63 via 2x4 wmma 16x16x16 accumulators.
// A: smem fp16 row-major ld=136. B: d_wh[n][k] -> smem fp16, col_major fragments ld=136.
// C staged to smem f32 (aliases A/B region after sync), then dinv-scale + fp16 pack.
#define ALD 136
#define SM_SSC 0
#define SM_SSH 512
#define SM_AB  1024
#define SM_BOFF (128 * ALD * 2)                 // bytes from SM_AB to B tile
#define MMA_SMEM_BYTES (1024 + 2 * 128 * ALD * 2)  // 70,656 B

__global__ __launch_bounds__(256) void k_gemm_mma(const float* __restrict__ x0, int layer) {
    extern __shared__ char smem[];
    float* ssc = (float*)(smem + SM_SSC);
    float* ssh = (float*)(smem + SM_SSH);
    __half* As = (__half*)(smem + SM_AB);
    __half* Bs = (__half*)(smem + SM_AB + SM_BOFF);
    float*  Cs = (float*)(smem + SM_AB);        // aliases A/B after mma completes

    int t = threadIdx.x;
    int wid = t >> 5;
    int blockRow = blockIdx.x * 128;

    if (t < 128) {
        ssc[t] = (layer != 0) ? d_scale[t] : 1.0f;
        ssh[t] = (layer != 0) ? d_shift[t] : 0.0f;
    }

    // B tile: d_wh[layer] (fp16 [n][k]) -> Bs[n*ALD + k]. 2048 uint4 / 256 = 8 each.
    {
        const uint4* src = (const uint4*)(d_wh + layer * HH * HH);
#pragma unroll
        for (int i = 0; i < 8; i++) {
            int f = t + i * 256;
            int n = f >> 4;
            int k8 = (f & 15) * 8;
            *(uint4*)&Bs[n * ALD + k8] = src[f];
        }
    }
    __syncthreads();  // ssc/ssh ready before A transform

    // A tile
    if (layer == 0) {
        // x fp32 -> fp16: 4096 float4 / 256 = 16 each
#pragma unroll
        for (int i = 0; i < 16; i++) {
            int f = t + i * 256;
            int r = f >> 5;
            int k4 = (f & 31) * 4;
            int gr = blockRow + r;
            float4 a = make_float4(0.f, 0.f, 0.f, 0.f);
            if (gr < NN) a = *(const float4*)&x0[gr * HH + k4];
            __half2 h0 = __floats2half2_rn(a.x, a.y);
            __half2 h1 = __floats2half2_rn(a.z, a.w);
            uint2 u;
            u.x = *(uint32_t*)&h0;
            u.y = *(uint32_t*)&h1;
            *(uint2*)&As[r * ALD + k4] = u;
        }
    } else {
        // d_preh fp16 with affine+relu folded: 2048 uint4 / 256 = 8 each
        const uint4* src = (const uint4*)d_preh;
#pragma unroll
        for (int i = 0; i < 8; i++) {
            int f = t + i * 256;
            int r = f >> 4;
            int k8 = (f & 15) * 8;
            int gr = blockRow + r;
            uint4 v = make_uint4(0u, 0u, 0u, 0u);
            if (gr < NN) {
                v = src[gr * 16 + (f & 15)];
                __half2* hp = (__half2*)&v;
#pragma unroll
                for (int p = 0; p < 4; p++) {
                    float2 f2 = __half22float2(hp[p]);
                    int kk = k8 + p * 2;
                    f2.x = fmaxf(fmaf(f2.x, ssc[kk], ssh[kk]), 0.f);
                    f2.y = fmaxf(fmaf(f2.y, ssc[kk + 1], ssh[kk + 1]), 0.f);
                    hp[p] = __floats2half2_rn(f2.x, f2.y);
                }
            }
            *(uint4*)&As[r * ALD + k8] = v;
        }
    }
    __syncthreads();

    // MMA: warp tile 32x64
    wmma::fragment<wmma::accumulator, 16, 16, 16, float> acc[2][4];
#pragma unroll
    for (int i = 0; i < 2; i++)
#pragma unroll
        for (int j = 0; j < 4; j++) wmma::fill_fragment(acc[i][j], 0.0f);

    int mbase = (wid & 3) * 32;
    int nbase = (wid >> 2) * 64;
#pragma unroll
    for (int k0 = 0; k0 < 128; k0 += 16) {
        wmma::fragment<wmma::matrix_a, 16, 16, 16, __half, wmma::row_major> af[2];
        wmma::load_matrix_sync(af[0], As + mbase * ALD + k0, ALD);
        wmma::load_matrix_sync(af[1], As + (mbase + 16) * ALD + k0, ALD);
        wmma::fragment<wmma::matrix_b, 16, 16, 16, __half, wmma::col_major> bf[4];
#pragma unroll
        for (int j = 0; j < 4; j++)
            wmma::load_matrix_sync(bf[j], Bs + (nbase + 16 * j) * ALD + k0, ALD);
#pragma unroll
        for (int i = 0; i < 2; i++)
#pragma unroll
            for (int j = 0; j < 4; j++)
                wmma::mma_sync(acc[i][j], af[i], bf[j], acc[i][j]);
    }
    __syncthreads();  // all warps done reading As/Bs before staging C there

#pragma unroll
    for (int i = 0; i < 2; i++)
#pragma unroll
        for (int j = 0; j < 4; j++)
            wmma::store_matrix_sync(Cs + (mbase + 16 * i) * 128 + nbase + 16 * j,
                                    acc[i][j], 128, wmma::mem_row_major);
    __syncthreads();

    // epilogue: thread t -> row t>>1, 64-col half (t&1); dinv scale + fp16 pack
    {
        int r = t >> 1;
        int ch = (t & 1) * 64;
        int gr = blockRow + r;
        if (gr < NN) {
            float dv = d_dinv[gr];
            __half* dst = d_gh + (size_t)gr * HH + ch;
            const float* srcc = Cs + r * 128 + ch;
#pragma unroll
            for (int q = 0; q < 8; q++) {
                float4 v0 = *(const float4*)&srcc[q * 8];
                float4 v1 = *(const float4*)&srcc[q * 8 + 4];
                __half2 h0 = __floats2half2_rn(v0.x * dv, v0.y * dv);
                __half2 h1 = __floats2half2_rn(v0.z * dv, v0.w * dv);
                __half2 h2 = __floats2half2_rn(v1.x * dv, v1.y * dv);
                __half2 h3 = __floats2half2_rn(v1.z * dv, v1.w * dv);
                *(uint4*)(dst + q * 8) = make_uint4(*(uint32_t*)&h0, *(uint32_t*)&h1,
                                                    *(uint32_t*)&h2, *(uint32_t*)&h3);
            }
        }
    }
}

// ---------------- aggregation + combine + BN stats (fp16 gathers) ----------------
#define AGG_ROWS 64
__global__ __launch_bounds__(256) void k_agg(const float* __restrict__ bias) {
    int t = threadIdx.x;
    int j = t & 63;
    int grp = t >> 6;
    int base = blockIdx.x * AGG_ROWS;
    const __half2* g2 = (const __half2*)d_gh;
    __half2* preh2 = (__half2*)d_preh;
    float bx = bias[2 * j], by = bias[2 * j + 1];
    float lsx = 0.f, lsy = 0.f, lqx = 0.f, lqy = 0.f;
#pragma unroll 1
    for (int r = grp; r < AGG_ROWS; r += 4) {
        int d = base + r;
        if (d >= NN) break;
        float2 sf = __half22float2(g2[d * 64 + j]);  // self-loop (already dinv-scaled)
        float a0x = sf.x, a0y = sf.y;
        float a1x = 0.f, a1y = 0.f, a2x = 0.f, a2y = 0.f, a3x = 0.f, a3y = 0.f;
        int s0 = d_rowstart[d];
        int cnt = d_deg[d];
        int e = 0;
        for (; e + 3 < cnt; e += 4) {
            int s1 = d_colsrc[s0 + e];
            int s2 = d_colsrc[s0 + e + 1];
            int s3 = d_colsrc[s0 + e + 2];
            int s4 = d_colsrc[s0 + e + 3];
            float2 v1 = __half22float2(g2[s1 * 64 + j]);
            float2 v2 = __half22float2(g2[s2 * 64 + j]);
            float2 v3 = __half22float2(g2[s3 * 64 + j]);
            float2 v4 = __half22float2(g2[s4 * 64 + j]);
            a0x += v1.x; a0y += v1.y;
            a1x += v2.x; a1y += v2.y;
            a2x += v3.x; a2y += v3.y;
            a3x += v4.x; a3y += v4.y;
        }
        for (; e < cnt; e++) {
            float2 v = __half22float2(g2[d_colsrc[s0 + e] * 64 + j]);
            a0x += v.x; a0y += v.y;
        }
        float dv = d_dinv[d];
        float vx = fmaf(dv, (a0x + a1x) + (a2x + a3x), bx);
        float vy = fmaf(dv, (a0y + a1y) + (a2y + a3y), by);
        preh2[d * 64 + j] = __floats2half2_rn(vx, vy);
        lsx += vx; lqx = fmaf(vx, vx, lqx);
        lsy += vy; lqy = fmaf(vy, vy, lqy);
    }
    atomicAdd(&d_bnsum[2 * j], lsx);
    atomicAdd(&d_bnsum[2 * j + 1], lsy);
    atomicAdd(&d_bnsq[2 * j], lqx);
    atomicAdd(&d_bnsq[2 * j + 1], lqy);
}

__global__ void k_bnfin(const float* __restrict__ gamma, const float* __restrict__ beta) {
    int j = threadIdx.x;
    float mean = d_bnsum[j] * (1.0f / NN);
    float var  = d_bnsq[j] * (1.0f / NN) - mean * mean;
    float s = gamma[j] * rsqrtf(var + BN_EPS);
    d_scale[j] = s;
    d_shift[j] = beta[j] - mean * s;
    // zero-after-read: steady-state invariant under graph replay
    d_bnsum[j] = 0.f;
    d_bnsq[j]  = 0.f;
}

// ---------------- global mean pool (batch is sorted) ----------------
#define POOL_R 256
__global__ void k_pool(const int* __restrict__ batch) {
    int j = threadIdx.x;  // 0..127
    int base = blockIdx.x * POOL_R;
    if (base >= NN) return;
    int end = base + POOL_R;
    if (end > NN) end = NN;
    int cur = batch[base];
    float acc = 0.f;
    int run = 0;
    float sc = d_scale[j], sh = d_shift[j];
    for (int row = base; row < end; row++) {
        int b = batch[row];
        if (b != cur) {
            atomicAdd(&d_pooled[cur * HH + j], acc);
            if (j == 0) atomicAdd(&d_cnt[cur], run);
            acc = 0.f; run = 0; cur = b;
        }
        float v = __half2float(d_preh[(size_t)row * HH + j]);
        v = fmaxf(fmaf(v, sc, sh), 0.f);
        acc += v;
        run++;
    }
    atomicAdd(&d_pooled[cur * HH + j], acc);
    if (j == 0) atomicAdd(&d_cnt[cur], run);
}

// ---------------- classifier MLP (zeroes its pooled row after reading) ----------------
__global__ void k_mlp(const float* __restrict__ w1, const float* __restrict__ b1,
                      const float* __restrict__ w2, const float* __restrict__ b2,
                      float* __restrict__ out) {
    __shared__ float p[128];
    __shared__ float z[64];
    int t = threadIdx.x;  // 0..63
    int g = blockIdx.x;
    float c = fmaxf((float)d_cnt[g], 1.0f);
    float inv = 1.0f / c;
    p[t]      = d_pooled[g * HH + t] * inv;
    p[t + 64] = d_pooled[g * HH + 64 + t] * inv;
    __syncthreads();
    d_pooled[g * HH + t] = 0.f;
    d_pooled[g * HH + 64 + t] = 0.f;
    if (t == 0) d_cnt[g] = 0;
    float a = b1[t];
#pragma unroll 8
    for (int k = 0; k < 128; k++) a = fmaf(p[k], w1[k * 64 + t], a);
    z[t] = fmaxf(a, 0.f);
    __syncthreads();
    if (t < CC) {
        float o = b2[t];
#pragma unroll
        for (int q = 0; q < 64; q++) o = fmaf(z[q], w2[q * CC + t], o);
        out[g * CC + t] = o;
    }
}

// ---------------- launch ----------------
extern "C" void kernel_launch(void* const* d_in, const int* in_sizes, int n_in,
                              void* d_out, int out_size) {
    const float* x      = (const float*)d_in[0];
    const float* conv_w = (const float*)d_in[1];
    const float* conv_b = (const float*)d_in[2];
    const float* bng    = (const float*)d_in[3];
    const float* bnb    = (const float*)d_in[4];
    const float* w1     = (const float*)d_in[5];
    const float* b1     = (const float*)d_in[6];
    const float* w2     = (const float*)d_in[7];
    const float* b2     = (const float*)d_in[8];
    const int*   ei     = (const int*)d_in[9];
    const int*   batch  = (const int*)d_in[10];
    float* out = (float*)d_out;

    cudaFuncSetAttribute(k_gemm_mma, cudaFuncAttributeMaxDynamicSharedMemorySize,
                         MMA_SMEM_BYTES);

    const int NB_SCAN = (NN + 1023) / 1024;            // 98
    const int GEMM_GRID = (NN + 127) / 128;            // 782

    // idx 0..3 arranged so ncu capture (launch index 3) profiles the wmma GEMM
    k_zero_deg<<<(NN + 255) / 256, 256>>>(conv_w);     // 0: deg=0 + W fp16 transpose
    k_count<<<(EE + 255) / 256, 256>>>(ei);            // 1
    k_scan1<<<NB_SCAN, 1024>>>();                      // 2: block sums + dinv
    k_gemm_mma<<<GEMM_GRID, 256, MMA_SMEM_BYTES>>>(x, 0);  // 3: layer-0 GEMM (profiled)
    k_scan2<<<1, 32>>>(NB_SCAN);                       // 4
    k_scan3<<<NB_SCAN, 1024>>>();                      // 5
    k_fill<<<(EE + 255) / 256, 256>>>(ei);             // 6

    for (int l = 0; l < LL; l++) {
        if (l > 0)
            k_gemm_mma<<<GEMM_GRID, 256, MMA_SMEM_BYTES>>>(x, l);
        k_agg<<<(NN + AGG_ROWS - 1) / AGG_ROWS, 256>>>(conv_b + l * HH);
        k_bnfin<<<1, 128>>>(bng + l * HH, bnb + l * HH);
    }

    k_pool<<<(NN + POOL_R - 1) / POOL_R, 128>>>(batch);
    k_mlp<<<GG, 64>>>(w1, b1, w2, b2, out);
}